// round 4
// baseline (speedup 1.0000x reference)
#include <cuda_runtime.h>
#include <math.h>

// Problem constants
#define PB 8
#define PN 2048
#define PM 2048
#define PC 512

// Scratch (static device globals; no runtime allocation)
__device__ float g_S[(long long)PB * PN * PM];   // masked scores / attn  (134 MB)
__device__ float g_V[(long long)PB * PM * PC];   // enc@Wv+bv             (33.5 MB)
__device__ float g_G[(long long)PB * PN * PC];   // gated                 (33.5 MB)
__device__ float g_H[(long long)PB * PN * PC];   // relu(fc1)             (33.5 MB)

// ---------------------------------------------------------------------------
// Generic tiled SIMT GEMM: C = A (Mr x K) @ B (K x Nc  or  Nc x K if TRB)
// Tile 128x128, BK=8, 256 threads, 8x8 per thread.
// EPI: 1 = +bias ; 2 = relu(+bias) ; 3 = gate: E*tanh(acc)+E ; 4 = acc*E (mask)
// All dims assumed multiples of tile sizes (true for this problem).
// ---------------------------------------------------------------------------
template <bool TRB, int EPI>
__global__ __launch_bounds__(256, 2)
void gemm_kernel(const float* __restrict__ Ag, const float* __restrict__ Bg,
                 float* __restrict__ Cg,
                 const float* __restrict__ bias, const float* __restrict__ Eg,
                 int K, int ldb, int ldc,
                 long long sA, long long sB, long long sC, long long sE)
{
    const int BM = 128, BN = 128, BK = 8;
    __shared__ float As[BK][BM + 4];
    __shared__ float Bs[BK][BN + 4];

    const int b = blockIdx.z;
    const float* A = Ag + b * sA + (long long)blockIdx.y * BM * K;
    const float* Bp;
    if (TRB) Bp = Bg + b * sB + (long long)blockIdx.x * BN * K;   // B rows along N, row-stride K
    else     Bp = Bg + b * sB + blockIdx.x * BN;                  // B is K x ldb
    float* C = Cg + b * sC + (long long)blockIdx.y * BM * ldc + blockIdx.x * BN;
    const float* E = nullptr;
    if (EPI == 3 || EPI == 4)
        E = Eg + b * sE + (long long)blockIdx.y * BM * ldc + blockIdx.x * BN;

    const int tid = threadIdx.x;
    const int tx = tid & 15;        // 16 col groups
    const int ty = tid >> 4;        // 16 row groups
    const int arow = tid >> 1;      // 0..127
    const int akc  = (tid & 1) * 4; // 0 or 4

    float acc[8][8];
#pragma unroll
    for (int i = 0; i < 8; i++)
#pragma unroll
        for (int j = 0; j < 8; j++) acc[i][j] = 0.0f;

    for (int k0 = 0; k0 < K; k0 += BK) {
        // Load A tile (BM x BK), store transposed
        {
            float4 av = *(const float4*)(A + (long long)arow * K + k0 + akc);
            As[akc + 0][arow] = av.x;
            As[akc + 1][arow] = av.y;
            As[akc + 2][arow] = av.z;
            As[akc + 3][arow] = av.w;
        }
        if (TRB) {
            // B tile is BN x BK (rows along output cols), store transposed
            float4 bv = *(const float4*)(Bp + (long long)arow * K + k0 + akc);
            Bs[akc + 0][arow] = bv.x;
            Bs[akc + 1][arow] = bv.y;
            Bs[akc + 2][arow] = bv.z;
            Bs[akc + 3][arow] = bv.w;
        } else {
            // B tile is BK x BN, direct vectorized store
            const int brow = tid >> 5;          // 0..7
            const int bc   = (tid & 31) * 4;    // 0..124
            float4 bv = *(const float4*)(Bp + (long long)(k0 + brow) * ldb + bc);
            *(float4*)&Bs[brow][bc] = bv;
        }
        __syncthreads();

#pragma unroll
        for (int kk = 0; kk < BK; kk++) {
            float ra[8], rb[8];
            *(float4*)(ra)     = *(const float4*)&As[kk][ty * 8];
            *(float4*)(ra + 4) = *(const float4*)&As[kk][ty * 8 + 4];
            *(float4*)(rb)     = *(const float4*)&Bs[kk][tx * 8];
            *(float4*)(rb + 4) = *(const float4*)&Bs[kk][tx * 8 + 4];
#pragma unroll
            for (int i = 0; i < 8; i++)
#pragma unroll
                for (int j = 0; j < 8; j++)
                    acc[i][j] = fmaf(ra[i], rb[j], acc[i][j]);
        }
        __syncthreads();
    }

    // Epilogue
#pragma unroll
    for (int i = 0; i < 8; i++) {
        const int r = ty * 8 + i;
#pragma unroll
        for (int jj = 0; jj < 8; jj += 4) {
            float o[4];
            float4 ev;
            if (EPI == 3 || EPI == 4)
                ev = *(const float4*)(E + (long long)r * ldc + tx * 8 + jj);
            const float* evp = &ev.x;
#pragma unroll
            for (int q = 0; q < 4; q++) {
                const int c = tx * 8 + jj + q;
                float v = acc[i][jj + q];
                if (EPI == 1) {
                    o[q] = v + bias[blockIdx.x * BN + c];
                } else if (EPI == 2) {
                    float t = v + bias[blockIdx.x * BN + c];
                    o[q] = t > 0.0f ? t : 0.0f;
                } else if (EPI == 3) {
                    float d = evp[q];
                    o[q] = d * tanhf(v) + d;
                } else { // EPI == 4
                    o[q] = v * evp[q];
                }
            }
            float4 ov = make_float4(o[0], o[1], o[2], o[3]);
            *(float4*)(C + (long long)r * ldc + tx * 8 + jj) = ov;
        }
    }
}

// ---------------------------------------------------------------------------
// Nonstandard masked softmax, in place, one block per row of 2048.
// softmax over ALL entries (zeros contribute exp(0-max)); then re-zero
// positions where the input value was exactly 0.
// ---------------------------------------------------------------------------
__global__ void softmax_kernel(float* __restrict__ S)
{
    const long long row = blockIdx.x;
    float* p = S + row * (long long)PM;
    const int tid = threadIdx.x;                 // 256 threads
    float4 a = ((const float4*)p)[tid * 2];
    float4 bq = ((const float4*)p)[tid * 2 + 1];
    float s[8] = {a.x, a.y, a.z, a.w, bq.x, bq.y, bq.z, bq.w};

    float mx = s[0];
#pragma unroll
    for (int i = 1; i < 8; i++) mx = fmaxf(mx, s[i]);
#pragma unroll
    for (int o = 16; o > 0; o >>= 1)
        mx = fmaxf(mx, __shfl_xor_sync(0xffffffffu, mx, o));
    __shared__ float smx[8];
    __shared__ float ssum[8];
    const int w = tid >> 5, l = tid & 31;
    if (l == 0) smx[w] = mx;
    __syncthreads();
    mx = smx[0];
#pragma unroll
    for (int i = 1; i < 8; i++) mx = fmaxf(mx, smx[i]);

    float e[8];
    float lsum = 0.0f;
#pragma unroll
    for (int i = 0; i < 8; i++) { e[i] = expf(s[i] - mx); lsum += e[i]; }
#pragma unroll
    for (int o = 16; o > 0; o >>= 1)
        lsum += __shfl_xor_sync(0xffffffffu, lsum, o);
    if (l == 0) ssum[w] = lsum;
    __syncthreads();
    float tot = 0.0f;
#pragma unroll
    for (int i = 0; i < 8; i++) tot += ssum[i];
    const float inv = 1.0f / tot;

    float r[8];
#pragma unroll
    for (int i = 0; i < 8; i++)
        r[i] = (s[i] != 0.0f) ? e[i] * inv : 0.0f;
    ((float4*)p)[tid * 2]     = make_float4(r[0], r[1], r[2], r[3]);
    ((float4*)p)[tid * 2 + 1] = make_float4(r[4], r[5], r[6], r[7]);
}

// ---------------------------------------------------------------------------
extern "C" void kernel_launch(void* const* d_in, const int* in_sizes, int n_in,
                              void* d_out, int out_size)
{
    const float* dec   = (const float*)d_in[0];  // [B,N,C]
    const float* enc   = (const float*)d_in[1];  // [B,M,C]
    const float* trans = (const float*)d_in[2];  // [B,N,M]
    const float* Wv    = (const float*)d_in[3];  // [C,C]
    const float* bv    = (const float*)d_in[4];  // [C]
    const float* W1    = (const float*)d_in[5];
    const float* b1    = (const float*)d_in[6];
    const float* W2    = (const float*)d_in[7];
    const float* b2    = (const float*)d_in[8];
    float* out = (float*)d_out;

    float *S, *V, *G, *H;
    cudaGetSymbolAddress((void**)&S, g_S);
    cudaGetSymbolAddress((void**)&V, g_V);
    cudaGetSymbolAddress((void**)&G, g_G);
    cudaGetSymbolAddress((void**)&H, g_H);

    const long long sNC = (long long)PN * PC;
    const long long sMC = (long long)PM * PC;
    const long long sNM = (long long)PN * PM;

    // 1) V = enc @ Wv + bv     (flat [B*M, C] x [C, C])
    gemm_kernel<false, 1><<<dim3(PC / 128, (PB * PM) / 128, 1), 256>>>(
        enc, Wv, V, bv, nullptr, PC, PC, PC, 0, 0, 0, 0);

    // 2) S = (dec @ enc^T) * trans    (per batch, NT)
    gemm_kernel<true, 4><<<dim3(PM / 128, PN / 128, PB), 256>>>(
        dec, enc, S, nullptr, trans, PC, PC, PM, sNC, sMC, sNM, sNM);

    // 3) nonstandard masked softmax over rows of S
    softmax_kernel<<<PB * PN, 256>>>(S);

    // 4) G = dec * tanh(S @ V) + dec   (per batch, K = M)
    gemm_kernel<false, 3><<<dim3(PC / 128, PN / 128, PB), 256>>>(
        S, V, G, nullptr, dec, PM, PC, PC, sNM, sMC, sNC, sNC);

    // 5) H = relu(G @ W1 + b1)   (flat)
    gemm_kernel<false, 2><<<dim3(PC / 128, (PB * PN) / 128, 1), 256>>>(
        G, W1, H, b1, nullptr, PC, PC, PC, 0, 0, 0, 0);

    // 6) out = H @ W2 + b2       (flat)
    gemm_kernel<false, 1><<<dim3(PC / 128, (PB * PN) / 128, 1), 256>>>(
        H, W2, out, b2, nullptr, PC, PC, PC, 0, 0, 0, 0);
}

// round 5
// speedup vs baseline: 3.0592x; 3.0592x over previous
#include <cuda_runtime.h>
#include <math.h>
#include <stdint.h>

// Problem constants
#define PB 8
#define PN 2048
#define PM 2048
#define PC 512

// Scratch (static device globals; no runtime allocation)
__device__ float g_S[(long long)PB * PN * PM];   // masked scores / attn  (134 MB)
__device__ float g_V[(long long)PB * PM * PC];   // enc@Wv+bv             (33.5 MB)
__device__ float g_G[(long long)PB * PN * PC];   // gated                 (33.5 MB)
__device__ float g_H[(long long)PB * PN * PC];   // relu(fc1)             (33.5 MB)

// ---------------------------------------------------------------------------
// helpers
// ---------------------------------------------------------------------------
__device__ __forceinline__ uint32_t smem_u32(const void* p) {
    uint32_t a;
    asm("{ .reg .u64 t; cvta.to.shared.u64 t, %1; cvt.u32.u64 %0, t; }"
        : "=r"(a) : "l"(p));
    return a;
}
__device__ __forceinline__ void cp16(uint32_t dst, const void* src) {
    asm volatile("cp.async.ca.shared.global [%0], [%1], 16;\n" :: "r"(dst), "l"(src));
}
__device__ __forceinline__ void cp_commit() { asm volatile("cp.async.commit_group;\n"); }
template <int N>
__device__ __forceinline__ void cp_wait() { asm volatile("cp.async.wait_group %0;\n" :: "n"(N)); }

__device__ __forceinline__ uint32_t f2tf(float x) {
    uint32_t u;
    asm("cvt.rna.tf32.f32 %0, %1;" : "=r"(u) : "f"(x));
    return u;
}
__device__ __forceinline__ void mma_tf32(float* c, const uint32_t* a, const uint32_t* b) {
    asm volatile(
        "mma.sync.aligned.m16n8k8.row.col.f32.tf32.tf32.f32 "
        "{%0,%1,%2,%3}, {%4,%5,%6,%7}, {%8,%9}, {%0,%1,%2,%3};"
        : "+f"(c[0]), "+f"(c[1]), "+f"(c[2]), "+f"(c[3])
        : "r"(a[0]), "r"(a[1]), "r"(a[2]), "r"(a[3]), "r"(b[0]), "r"(b[1]));
}

// ---------------------------------------------------------------------------
// tf32 tensor-core GEMM: C = A (Mr x K) @ B  (+ epilogue)
//   TRB=false: B is K x Nc row-major (k-major).   TRB=true: B is Nc x K row-major.
// Tile 128x128, BK=16, 256 threads (8 warps, 2x4), warp tile m64n32, mma m16n8k8.
// EPI: 1 = +bias ; 2 = relu(+bias) ; 3 = gate: E*tanh(acc)+E ; 4 = acc*E (mask)
// All dims multiples of tile sizes. A fragment smem stride 20 and B-NN stride 136
// are chosen so all fragment LDS are bank-conflict-free.
// ---------------------------------------------------------------------------
template <bool TRB, int EPI>
__global__ __launch_bounds__(256)
void mma_gemm(const float* __restrict__ Ag, const float* __restrict__ Bg,
              float* __restrict__ Cg,
              const float* __restrict__ bias, const float* __restrict__ Eg,
              int K, int ldb, int ldc,
              long long sA, long long sB, long long sC, long long sE)
{
    constexpr int BM = 128, BN = 128, BK = 16;
    constexpr int ASTR = 20;                      // floats per A smem row
    constexpr int BSTR = TRB ? 20 : 136;          // floats per B smem row
    constexpr int BELEMS = TRB ? 128 * 20 : 16 * 136;

    __shared__ float As[2][128 * ASTR];
    __shared__ float Bs[2][BELEMS];

    const int b = blockIdx.z;
    const int bm = blockIdx.y * BM;
    const int bn = blockIdx.x * BN;
    const float* A = Ag + b * sA + (long long)bm * K;
    const float* Bp = TRB ? (Bg + b * sB + (long long)bn * K)
                          : (Bg + b * sB + bn);
    float* C = Cg + b * sC + (long long)bm * ldc + bn;
    const float* E = (EPI == 3 || EPI == 4)
                         ? (Eg + b * sE + (long long)bm * ldc + bn) : nullptr;

    const int tid = threadIdx.x;
    const int warp = tid >> 5, lane = tid & 31;
    const int wm = warp >> 2, wn = warp & 3;      // 2 x 4 warp grid
    const int g = lane >> 2, tg = lane & 3;       // groupID, threadID-in-group

    const uint32_t sA0 = smem_u32(&As[0][0]);
    const uint32_t sB0 = smem_u32(&Bs[0][0]);

    float acc[4][4][4];
#pragma unroll
    for (int i = 0; i < 4; i++)
#pragma unroll
        for (int j = 0; j < 4; j++)
#pragma unroll
            for (int q = 0; q < 4; q++) acc[i][j][q] = 0.0f;

    const int NK = K / BK;

    auto load_stage = [&](int kt, int bb) {
        const int k0 = kt * BK;
#pragma unroll
        for (int r = 0; r < 2; r++) {
            const int fid = tid + r * 256;                 // 0..511
            const int m = fid >> 2, kq = fid & 3;          // A: 128 rows x 4 float4
            cp16(sA0 + (uint32_t)(bb * 128 * ASTR + m * ASTR + kq * 4) * 4u,
                 A + (long long)m * K + k0 + kq * 4);
            if (TRB) {
                cp16(sB0 + (uint32_t)(bb * BELEMS + m * BSTR + kq * 4) * 4u,
                     Bp + (long long)m * K + k0 + kq * 4);
            } else {
                const int kk = fid >> 5, nq = fid & 31;    // 16 rows x 32 float4
                cp16(sB0 + (uint32_t)(bb * BELEMS + kk * BSTR + nq * 4) * 4u,
                     Bp + (long long)(k0 + kk) * ldb + nq * 4);
            }
        }
    };

    auto compute_stage = [&](int bb) {
        const float* __restrict__ Ab = &As[bb][0];
        const float* __restrict__ Bb = &Bs[bb][0];
#pragma unroll
        for (int ks = 0; ks < BK; ks += 8) {
            uint32_t ua[4][4], ub[4][2];
#pragma unroll
            for (int i = 0; i < 4; i++) {
                const int r0 = wm * 64 + i * 16 + g;
                ua[i][0] = f2tf(Ab[r0 * ASTR + ks + tg]);
                ua[i][1] = f2tf(Ab[(r0 + 8) * ASTR + ks + tg]);
                ua[i][2] = f2tf(Ab[r0 * ASTR + ks + tg + 4]);
                ua[i][3] = f2tf(Ab[(r0 + 8) * ASTR + ks + tg + 4]);
            }
#pragma unroll
            for (int j = 0; j < 4; j++) {
                const int n = wn * 32 + j * 8 + g;
                if (TRB) {
                    ub[j][0] = f2tf(Bb[n * BSTR + ks + tg]);
                    ub[j][1] = f2tf(Bb[n * BSTR + ks + tg + 4]);
                } else {
                    ub[j][0] = f2tf(Bb[(ks + tg) * BSTR + n]);
                    ub[j][1] = f2tf(Bb[(ks + tg + 4) * BSTR + n]);
                }
            }
#pragma unroll
            for (int i = 0; i < 4; i++)
#pragma unroll
                for (int j = 0; j < 4; j++)
                    mma_tf32(acc[i][j], ua[i], ub[j]);
        }
    };

    load_stage(0, 0);
    cp_commit();
    int buf = 0;
    for (int kt = 0; kt < NK; kt++) {
        if (kt + 1 < NK) {
            load_stage(kt + 1, buf ^ 1);
            cp_commit();
            cp_wait<1>();
        } else {
            cp_wait<0>();
        }
        __syncthreads();
        compute_stage(buf);
        __syncthreads();
        buf ^= 1;
    }

    // Epilogue: each (i,j) tile -> rows r0, r0+8 ; cols c, c+1 (float2 stores)
#pragma unroll
    for (int i = 0; i < 4; i++) {
        const int r0 = wm * 64 + i * 16 + g;
#pragma unroll
        for (int j = 0; j < 4; j++) {
            const int c = wn * 32 + j * 8 + 2 * tg;
            float v0 = acc[i][j][0], v1 = acc[i][j][1];
            float v2 = acc[i][j][2], v3 = acc[i][j][3];
            float2 o0, o1;
            if (EPI == 1 || EPI == 2) {
                const float bb0 = bias[bn + c], bb1 = bias[bn + c + 1];
                o0 = make_float2(v0 + bb0, v1 + bb1);
                o1 = make_float2(v2 + bb0, v3 + bb1);
                if (EPI == 2) {
                    o0.x = fmaxf(o0.x, 0.0f); o0.y = fmaxf(o0.y, 0.0f);
                    o1.x = fmaxf(o1.x, 0.0f); o1.y = fmaxf(o1.y, 0.0f);
                }
            } else {
                const float2 d0 = *(const float2*)(E + (long long)r0 * ldc + c);
                const float2 d1 = *(const float2*)(E + (long long)(r0 + 8) * ldc + c);
                if (EPI == 3) {
                    o0 = make_float2(d0.x * tanhf(v0) + d0.x, d0.y * tanhf(v1) + d0.y);
                    o1 = make_float2(d1.x * tanhf(v2) + d1.x, d1.y * tanhf(v3) + d1.y);
                } else { // EPI == 4
                    o0 = make_float2(v0 * d0.x, v1 * d0.y);
                    o1 = make_float2(v2 * d1.x, v3 * d1.y);
                }
            }
            *(float2*)(C + (long long)r0 * ldc + c) = o0;
            *(float2*)(C + (long long)(r0 + 8) * ldc + c) = o1;
        }
    }
}

// ---------------------------------------------------------------------------
// Nonstandard masked softmax, in place, one block per row of 2048.
// softmax over ALL entries (zeros contribute exp(0-max)); then re-zero
// positions where the input value was exactly 0.
// ---------------------------------------------------------------------------
__global__ void softmax_kernel(float* __restrict__ S)
{
    const long long row = blockIdx.x;
    float* p = S + row * (long long)PM;
    const int tid = threadIdx.x;                 // 256 threads
    float4 a = ((const float4*)p)[tid * 2];
    float4 bq = ((const float4*)p)[tid * 2 + 1];
    float s[8] = {a.x, a.y, a.z, a.w, bq.x, bq.y, bq.z, bq.w};

    float mx = s[0];
#pragma unroll
    for (int i = 1; i < 8; i++) mx = fmaxf(mx, s[i]);
#pragma unroll
    for (int o = 16; o > 0; o >>= 1)
        mx = fmaxf(mx, __shfl_xor_sync(0xffffffffu, mx, o));
    __shared__ float smx[8];
    __shared__ float ssum[8];
    const int w = tid >> 5, l = tid & 31;
    if (l == 0) smx[w] = mx;
    __syncthreads();
    mx = smx[0];
#pragma unroll
    for (int i = 1; i < 8; i++) mx = fmaxf(mx, smx[i]);

    float e[8];
    float lsum = 0.0f;
#pragma unroll
    for (int i = 0; i < 8; i++) { e[i] = expf(s[i] - mx); lsum += e[i]; }
#pragma unroll
    for (int o = 16; o > 0; o >>= 1)
        lsum += __shfl_xor_sync(0xffffffffu, lsum, o);
    if (l == 0) ssum[w] = lsum;
    __syncthreads();
    float tot = 0.0f;
#pragma unroll
    for (int i = 0; i < 8; i++) tot += ssum[i];
    const float inv = 1.0f / tot;

    float r[8];
#pragma unroll
    for (int i = 0; i < 8; i++)
        r[i] = (s[i] != 0.0f) ? e[i] * inv : 0.0f;
    ((float4*)p)[tid * 2]     = make_float4(r[0], r[1], r[2], r[3]);
    ((float4*)p)[tid * 2 + 1] = make_float4(r[4], r[5], r[6], r[7]);
}

// ---------------------------------------------------------------------------
extern "C" void kernel_launch(void* const* d_in, const int* in_sizes, int n_in,
                              void* d_out, int out_size)
{
    const float* dec   = (const float*)d_in[0];  // [B,N,C]
    const float* enc   = (const float*)d_in[1];  // [B,M,C]
    const float* trans = (const float*)d_in[2];  // [B,N,M]
    const float* Wv    = (const float*)d_in[3];  // [C,C]
    const float* bv    = (const float*)d_in[4];  // [C]
    const float* W1    = (const float*)d_in[5];
    const float* b1    = (const float*)d_in[6];
    const float* W2    = (const float*)d_in[7];
    const float* b2    = (const float*)d_in[8];
    float* out = (float*)d_out;

    float *S, *V, *G, *H;
    cudaGetSymbolAddress((void**)&S, g_S);
    cudaGetSymbolAddress((void**)&V, g_V);
    cudaGetSymbolAddress((void**)&G, g_G);
    cudaGetSymbolAddress((void**)&H, g_H);

    const long long sNC = (long long)PN * PC;
    const long long sMC = (long long)PM * PC;
    const long long sNM = (long long)PN * PM;

    // 1) V = enc @ Wv + bv     (flat [B*M, C] x [C, C], NN)
    mma_gemm<false, 1><<<dim3(PC / 128, (PB * PM) / 128, 1), 256>>>(
        enc, Wv, V, bv, nullptr, PC, PC, PC, 0, 0, 0, 0);

    // 2) S = (dec @ enc^T) * trans    (per batch, NT)
    mma_gemm<true, 4><<<dim3(PM / 128, PN / 128, PB), 256>>>(
        dec, enc, S, nullptr, trans, PC, PC, PM, sNC, sMC, sNM, sNM);

    // 3) nonstandard masked softmax over rows of S
    softmax_kernel<<<PB * PN, 256>>>(S);

    // 4) G = dec * tanh(S @ V) + dec   (per batch, NN, K = M)
    mma_gemm<false, 3><<<dim3(PC / 128, PN / 128, PB), 256>>>(
        S, V, G, nullptr, dec, PM, PC, PC, sNM, sMC, sNC, sNC);

    // 5) H = relu(G @ W1 + b1)   (flat NN)
    mma_gemm<false, 2><<<dim3(PC / 128, (PB * PN) / 128, 1), 256>>>(
        G, W1, H, b1, nullptr, PC, PC, PC, 0, 0, 0, 0);

    // 6) out = H @ W2 + b2       (flat NN)
    mma_gemm<false, 1><<<dim3(PC / 128, (PB * PN) / 128, 1), 256>>>(
        H, W2, out, b2, nullptr, PC, PC, PC, 0, 0, 0, 0);
}